// round 14
// baseline (speedup 1.0000x reference)
#include <cuda_runtime.h>
#include <cuda_fp16.h>
#include <cstdint>

#define NT    8192
#define DIM   1024
#define INTER 4096
#define NE    8
#define MAXROWS  17408      // 2*NT + NE*128 (expert segments padded to 128)
#define MAXTILES 136        // MAXROWS/128

// ---------------- scratch (device globals: no allocations allowed) ----------------
__device__ __half g_xh[(size_t)NT * DIM];
__device__ __half g_Hs[(size_t)NT * INTER];                // shared-expert H (s-chain)
__device__ __half g_H[(size_t)MAXROWS * INTER];            // routed gathered H (r-chain)
__device__ __half g_w1t[(size_t)(NE + 1) * INTER * DIM];   // [1+E][INTER][DIM]  (W1^T, K-major)
__device__ __half g_w2t[(size_t)(NE + 1) * DIM * INTER];   // [1+E][DIM][INTER]  (W2^T, K-major)
__device__ float  g_P[(size_t)MAXROWS * DIM];              // routed partials (permuted rows)
__device__ int    g_perm[MAXROWS];
__device__ float  g_wperm[MAXROWS];
__device__ int    g_pos[NT * 2];
__device__ int    g_tok_e[NT * 2];
__device__ float  g_tok_w[NT * 2];
__device__ int    g_cnt[NE];
__device__ int    g_cursor[NE];
__device__ int    g_tile_e[MAXTILES];
__device__ int    g_tile_m[MAXTILES];

// ---------------- PTX helpers ----------------
__device__ __forceinline__ uint32_t smem_u32(const void* p) {
    uint32_t a;
    asm("{ .reg .u64 t; cvta.to.shared.u64 t, %1; cvt.u32.u64 %0, t; }" : "=r"(a) : "l"(p));
    return a;
}
__device__ __forceinline__ void ldm4(uint32_t* r, uint32_t addr) {
    asm volatile("ldmatrix.sync.aligned.m8n8.x4.shared.b16 {%0,%1,%2,%3}, [%4];"
                 : "=r"(r[0]), "=r"(r[1]), "=r"(r[2]), "=r"(r[3]) : "r"(addr));
}
__device__ __forceinline__ void mma16816(float* d, const uint32_t* a, uint32_t b0, uint32_t b1) {
    asm volatile(
        "mma.sync.aligned.m16n8k16.row.col.f32.f16.f16.f32 "
        "{%0,%1,%2,%3},{%4,%5,%6,%7},{%8,%9},{%0,%1,%2,%3};"
        : "+f"(d[0]), "+f"(d[1]), "+f"(d[2]), "+f"(d[3])
        : "r"(a[0]), "r"(a[1]), "r"(a[2]), "r"(a[3]), "r"(b0), "r"(b1));
}
// fp16-accumulate variant: d/c are 2 regs (4 halves), same element mapping as f32 case
__device__ __forceinline__ void mma16816h(uint32_t* d, const uint32_t* a, uint32_t b0, uint32_t b1) {
    asm volatile(
        "mma.sync.aligned.m16n8k16.row.col.f16.f16.f16.f16 "
        "{%0,%1},{%2,%3,%4,%5},{%6,%7},{%0,%1};"
        : "+r"(d[0]), "+r"(d[1])
        : "r"(a[0]), "r"(a[1]), "r"(a[2]), "r"(a[3]), "r"(b0), "r"(b1));
}
__device__ __forceinline__ void cpa16(uint32_t dst, const void* src) {
    asm volatile("cp.async.cg.shared.global [%0], [%1], 16;" :: "r"(dst), "l"(src));
}

// ---------------- small kernels ----------------
__global__ void init_kernel() {
    int i = blockIdx.x * 256 + threadIdx.x;
    if (i < NE) g_cnt[i] = 0;
    if (i < MAXROWS) { g_perm[i] = 0; g_wperm[i] = 0.0f; }
}

__global__ void router_kernel(const float* __restrict__ x, const float* __restrict__ rw) {
    int w = (blockIdx.x * blockDim.x + threadIdx.x) >> 5;
    int lane = threadIdx.x & 31;
    if (w >= NT) return;
    const float* xr = x + (size_t)w * DIM;
    float acc[NE];
#pragma unroll
    for (int e = 0; e < NE; e++) acc[e] = 0.f;
    for (int k = lane; k < DIM; k += 32) {
        float xv = xr[k];
        const float4 wa = *(const float4*)(rw + k * NE);
        const float4 wb = *(const float4*)(rw + k * NE + 4);
        acc[0] += xv*wa.x; acc[1] += xv*wa.y; acc[2] += xv*wa.z; acc[3] += xv*wa.w;
        acc[4] += xv*wb.x; acc[5] += xv*wb.y; acc[6] += xv*wb.z; acc[7] += xv*wb.w;
    }
#pragma unroll
    for (int off = 16; off > 0; off >>= 1)
#pragma unroll
        for (int e = 0; e < NE; e++) acc[e] += __shfl_xor_sync(0xffffffffu, acc[e], off);
    if (lane == 0) {
        float v0 = -1e30f, v1 = -1e30f; int i0 = 0, i1 = 0;
#pragma unroll
        for (int e = 0; e < NE; e++) {
            float v = acc[e];
            if (v > v0) { v1 = v0; i1 = i0; v0 = v; i0 = e; }
            else if (v > v1) { v1 = v; i1 = e; }
        }
        float w0 = 1.0f / (1.0f + expf(v1 - v0));
        float w1 = 1.0f - w0;
        g_tok_e[2*w] = i0; g_tok_e[2*w+1] = i1;
        g_tok_w[2*w] = w0; g_tok_w[2*w+1] = w1;
        atomicAdd(&g_cnt[i0], 1); atomicAdd(&g_cnt[i1], 1);
    }
}

__global__ void scan_kernel() {
    if (threadIdx.x != 0 || blockIdx.x != 0) return;
    int off = 0, tile = 0;
    for (int e = 0; e < NE; e++) {
        int c = g_cnt[e];
        g_cursor[e] = off;
        int nt = (c + 127) >> 7;
        for (int i = 0; i < nt; i++) {
            g_tile_e[tile] = e; g_tile_m[tile] = off + (i << 7); tile++;
        }
        off += nt << 7;
    }
    for (; tile < MAXTILES; tile++) g_tile_e[tile] = -1;
}

__global__ void scatter_kernel() {
    int t = blockIdx.x * 256 + threadIdx.x;
    if (t >= NT) return;
#pragma unroll
    for (int k = 0; k < 2; k++) {
        int e = g_tok_e[2*t + k];
        int p = atomicAdd(&g_cursor[e], 1);
        g_perm[p] = t;
        g_wperm[p] = g_tok_w[2*t + k];
        g_pos[2*t + k] = p;
    }
}

__global__ void cvtx_kernel(const float* __restrict__ x) {
    size_t i = ((size_t)blockIdx.x * 256 + threadIdx.x) * 4;
    float4 v = *(const float4*)(x + i);
    union { __half2 h[2]; uint2 u; } pk;
    pk.h[0] = __floats2half2_rn(v.x, v.y);
    pk.h[1] = __floats2half2_rn(v.z, v.w);
    *(uint2*)(g_xh + i) = pk.u;
}

// transpose + convert: in fp32 [R,C] (row-major) -> out fp16 [C,R] (K-major for MMA)
__global__ void tcvt_kernel(const float* __restrict__ in, int w2sel, size_t outOff, int R, int C) {
    __shared__ float t[64][65];
    int z = blockIdx.z;
    in += (size_t)z * R * C;
    __half* out = (w2sel ? g_w2t : g_w1t) + outOff + (size_t)z * R * C;
    int r0 = blockIdx.y * 64, c0 = blockIdx.x * 64;
    int tx = threadIdx.x, ty = threadIdx.y;
#pragma unroll
    for (int i = 0; i < 8; i++) {
        int row = ty + i * 8;
        const float* p = in + (size_t)(r0 + row) * C + c0 + tx;
        t[row][tx]      = p[0];
        t[row][tx + 32] = p[32];
    }
    __syncthreads();
#pragma unroll
    for (int i = 0; i < 8; i++) {
        int c = ty + i * 8;
        __half2 v = __floats2half2_rn(t[2*tx][c], t[2*tx + 1][c]);
        *(__half2*)(out + (size_t)(c0 + c) * R + r0 + 2*tx) = v;
    }
}

__global__ void combine_kernel(float* __restrict__ out) {
    int t = blockIdx.x;
    int c = threadIdx.x * 4;
    int p0 = g_pos[2*t], p1 = g_pos[2*t + 1];
    float w0 = g_wperm[p0], w1 = g_wperm[p1];
    float4 o = *(float4*)(out + (size_t)t * DIM + c);
    float4 a = *(const float4*)(g_P + (size_t)p0 * DIM + c);
    float4 b = *(const float4*)(g_P + (size_t)p1 * DIM + c);
    o.x += w0*a.x + w1*b.x; o.y += w0*a.y + w1*b.y;
    o.z += w0*a.z + w1*b.z; o.w += w0*a.w + w1*b.w;
    *(float4*)(out + (size_t)t * DIM + c) = o;
}

// ---------------- fp16 HMMA GEMM (narrow, f32-acc): BM=BN=128, BK=64, warp 32x64, 2 CTA/SM ------
// ASRC: 0 -> g_xh, 1 -> g_Hs, 2 -> g_H
// CDST: 0 -> g_Hs (fp16, relu), 1 -> outp (fp32), 2 -> g_P (fp32), 3 -> g_H (fp16, relu)
template<int KD, int ND, bool GROUPED, bool GATHER, bool RELU, int CDST, int ASRC, bool W1SEL>
__global__ void __launch_bounds__(256, 2) gemm_hmma(float* __restrict__ outp) {
    constexpr int BK = 64, KT = KD / BK;
    constexpr int AST = 72;
    constexpr int TILEB = 128 * AST * 2;
    constexpr int STAGEB = 2 * TILEB;
    extern __shared__ __half sm[];

    const __half* A = (ASRC == 0) ? g_xh : ((ASRC == 1) ? g_Hs : g_H);
    const __half* B = W1SEL ? g_w1t : g_w2t;
    int mbase;
    if (GROUPED) {
        int e = g_tile_e[blockIdx.y];
        if (e < 0) return;
        mbase = g_tile_m[blockIdx.y];
        B += (size_t)(1 + e) * KD * ND;
    } else {
        mbase = blockIdx.y * 128;
    }
    const int nbase = blockIdx.x * 128;
    const int tid = threadIdx.x, warp = tid >> 5, lane = tid & 31;
    const int wr = warp & 3, wc = warp >> 2;
    const int g = lane >> 2, tg = lane & 3;

    const __half* aPtr[4]; const __half* bPtr[4];
    uint32_t sAoff[4], sBoff[4];
    const uint32_t smb = smem_u32(sm);
#pragma unroll
    for (int i = 0; i < 4; i++) {
        int idx = tid + i * 256, row = idx >> 3, ch = idx & 7;
        sAoff[i] = smb + (row * AST + ch * 8) * 2;
        sBoff[i] = sAoff[i] + TILEB;
        int ar = mbase + row;
        if (GATHER) ar = g_perm[ar];
        aPtr[i] = A + (size_t)ar * KD + ch * 8;
        bPtr[i] = B + (size_t)(nbase + row) * KD + ch * 8;
    }

    const int lr = (lane & 7) + ((lane >> 3) & 1) * 8;
    const int lk = (lane >> 4) * 8;
    const uint32_t aBase = smb + ((wr * 32 + lr) * AST + lk) * 2;
    const uint32_t bBase = smb + TILEB + ((wc * 64 + lr) * AST + lk) * 2;
    constexpr int ROW16 = 16 * AST * 2;

    float acc[2][8][4];
#pragma unroll
    for (int a = 0; a < 2; a++)
#pragma unroll
        for (int b = 0; b < 8; b++)
#pragma unroll
            for (int c = 0; c < 4; c++) acc[a][b][c] = 0.f;

#define ISSUE_STAGE_N(kt_, s_) do {                                           \
        uint32_t so_ = (uint32_t)(s_) * STAGEB;                               \
        _Pragma("unroll")                                                     \
        for (int i_ = 0; i_ < 4; i_++) cpa16(sAoff[i_] + so_, aPtr[i_] + (kt_) * BK); \
        _Pragma("unroll")                                                     \
        for (int i_ = 0; i_ < 4; i_++) cpa16(sBoff[i_] + so_, bPtr[i_] + (kt_) * BK); \
        asm volatile("cp.async.commit_group;" ::: "memory");                  \
    } while (0)

    ISSUE_STAGE_N(0, 0);
    ISSUE_STAGE_N(1, 1);

    int s = 0;
    for (int kt = 0; kt < KT; kt++) {
        if (kt + 1 < KT) asm volatile("cp.async.wait_group 1;" ::: "memory");
        else             asm volatile("cp.async.wait_group 0;" ::: "memory");
        __syncthreads();
        if (kt + 2 < KT) {
            int s2 = s + 2; if (s2 >= 3) s2 -= 3;
            ISSUE_STAGE_N(kt + 2, s2);
        }
        const uint32_t ab = aBase + s * STAGEB;
        const uint32_t bb = bBase + s * STAGEB;
#pragma unroll
        for (int kg = 0; kg < 4; kg++) {
            uint32_t af[2][4];
            ldm4(af[0], ab + kg * 32);
            ldm4(af[1], ab + ROW16 + kg * 32);
#pragma unroll
            for (int nj = 0; nj < 4; nj++) {
                uint32_t bf[4];
                ldm4(bf, bb + nj * ROW16 + kg * 32);
                mma16816(acc[0][2*nj],     af[0], bf[0], bf[2]);
                mma16816(acc[0][2*nj + 1], af[0], bf[1], bf[3]);
                mma16816(acc[1][2*nj],     af[1], bf[0], bf[2]);
                mma16816(acc[1][2*nj + 1], af[1], bf[1], bf[3]);
            }
        }
        s = (s + 1 == 3) ? 0 : s + 1;
    }
#undef ISSUE_STAGE_N

#pragma unroll
    for (int mi = 0; mi < 2; mi++) {
        const int r0 = mbase + wr * 32 + mi * 16 + g;
#pragma unroll
        for (int ni = 0; ni < 8; ni++) {
            const int c = nbase + wc * 64 + ni * 8 + tg * 2;
            float x0 = acc[mi][ni][0], x1 = acc[mi][ni][1];
            float x2 = acc[mi][ni][2], x3 = acc[mi][ni][3];
            if (RELU) { x0 = fmaxf(x0, 0.f); x1 = fmaxf(x1, 0.f);
                        x2 = fmaxf(x2, 0.f); x3 = fmaxf(x3, 0.f); }
            if (CDST == 0 || CDST == 3) {
                __half* H = (CDST == 0) ? g_Hs : g_H;
                *(__half2*)(H + (size_t)r0 * ND + c)       = __floats2half2_rn(x0, x1);
                *(__half2*)(H + (size_t)(r0 + 8) * ND + c) = __floats2half2_rn(x2, x3);
            } else {
                float* base = (CDST == 1) ? outp : (float*)g_P;
                *(float2*)(base + (size_t)r0 * ND + c)       = make_float2(x0, x1);
                *(float2*)(base + (size_t)(r0 + 8) * ND + c) = make_float2(x2, x3);
            }
        }
    }
}

// ---------------- LAYER-1 fp16-ACC EXPERIMENT: same tiling, f16.f16.f16.f16 MMA ----------------
// KD=DIM, A=g_xh, B=g_w1t, relu, fp16 H out. Promotes f16 chunk sums (K=64) into f32 per kt.
// CDST: 0 -> g_Hs, 3 -> g_H
template<bool GROUPED, bool GATHER, int CDST>
__global__ void __launch_bounds__(256, 1) gemm_h16acc() {
    constexpr int KD = DIM, ND = INTER;
    constexpr int BK = 64, KT = KD / BK;
    constexpr int AST = 72;
    constexpr int TILEB = 128 * AST * 2;
    constexpr int STAGEB = 2 * TILEB;
    extern __shared__ __half sm[];

    const __half* A = g_xh;
    const __half* B = g_w1t;
    int mbase;
    if (GROUPED) {
        int e = g_tile_e[blockIdx.y];
        if (e < 0) return;
        mbase = g_tile_m[blockIdx.y];
        B += (size_t)(1 + e) * KD * ND;
    } else {
        mbase = blockIdx.y * 128;
    }
    const int nbase = blockIdx.x * 128;
    const int tid = threadIdx.x, warp = tid >> 5, lane = tid & 31;
    const int wr = warp & 3, wc = warp >> 2;
    const int g = lane >> 2, tg = lane & 3;

    const __half* aPtr[4]; const __half* bPtr[4];
    uint32_t sAoff[4], sBoff[4];
    const uint32_t smb = smem_u32(sm);
#pragma unroll
    for (int i = 0; i < 4; i++) {
        int idx = tid + i * 256, row = idx >> 3, ch = idx & 7;
        sAoff[i] = smb + (row * AST + ch * 8) * 2;
        sBoff[i] = sAoff[i] + TILEB;
        int ar = mbase + row;
        if (GATHER) ar = g_perm[ar];
        aPtr[i] = A + (size_t)ar * KD + ch * 8;
        bPtr[i] = B + (size_t)(nbase + row) * KD + ch * 8;
    }

    const int lr = (lane & 7) + ((lane >> 3) & 1) * 8;
    const int lk = (lane >> 4) * 8;
    const uint32_t aBase = smb + ((wr * 32 + lr) * AST + lk) * 2;
    const uint32_t bBase = smb + TILEB + ((wc * 64 + lr) * AST + lk) * 2;
    constexpr int ROW16 = 16 * AST * 2;

    float facc[2][8][4];
#pragma unroll
    for (int a = 0; a < 2; a++)
#pragma unroll
        for (int b = 0; b < 8; b++)
#pragma unroll
            for (int c = 0; c < 4; c++) facc[a][b][c] = 0.f;

#define ISSUE_STAGE_H(kt_, s_) do {                                           \
        uint32_t so_ = (uint32_t)(s_) * STAGEB;                               \
        _Pragma("unroll")                                                     \
        for (int i_ = 0; i_ < 4; i_++) cpa16(sAoff[i_] + so_, aPtr[i_] + (kt_) * BK); \
        _Pragma("unroll")                                                     \
        for (int i_ = 0; i_ < 4; i_++) cpa16(sBoff[i_] + so_, bPtr[i_] + (kt_) * BK); \
        asm volatile("cp.async.commit_group;" ::: "memory");                  \
    } while (0)

    ISSUE_STAGE_H(0, 0);
    ISSUE_STAGE_H(1, 1);

    int s = 0;
    for (int kt = 0; kt < KT; kt++) {
        if (kt + 1 < KT) asm volatile("cp.async.wait_group 1;" ::: "memory");
        else             asm volatile("cp.async.wait_group 0;" ::: "memory");
        __syncthreads();
        if (kt + 2 < KT) {
            int s2 = s + 2; if (s2 >= 3) s2 -= 3;
            ISSUE_STAGE_H(kt + 2, s2);
        }
        const uint32_t ab = aBase + s * STAGEB;
        const uint32_t bb = bBase + s * STAGEB;

        uint32_t hacc[2][8][2];          // fp16x2 chunk accumulators, zeroed per kt
#pragma unroll
        for (int a = 0; a < 2; a++)
#pragma unroll
            for (int b = 0; b < 8; b++) { hacc[a][b][0] = 0u; hacc[a][b][1] = 0u; }

#pragma unroll
        for (int kg = 0; kg < 4; kg++) {
            uint32_t af[2][4];
            ldm4(af[0], ab + kg * 32);
            ldm4(af[1], ab + ROW16 + kg * 32);
#pragma unroll
            for (int nj = 0; nj < 4; nj++) {
                uint32_t bf[4];
                ldm4(bf, bb + nj * ROW16 + kg * 32);
                mma16816h(hacc[0][2*nj],     af[0], bf[0], bf[2]);
                mma16816h(hacc[0][2*nj + 1], af[0], bf[1], bf[3]);
                mma16816h(hacc[1][2*nj],     af[1], bf[0], bf[2]);
                mma16816h(hacc[1][2*nj + 1], af[1], bf[1], bf[3]);
            }
        }
        // promote chunk (K=64) into f32 master
#pragma unroll
        for (int a = 0; a < 2; a++)
#pragma unroll
            for (int b = 0; b < 8; b++) {
                float2 lo = __half22float2(*(__half2*)&hacc[a][b][0]);
                float2 hi = __half22float2(*(__half2*)&hacc[a][b][1]);
                facc[a][b][0] += lo.x; facc[a][b][1] += lo.y;
                facc[a][b][2] += hi.x; facc[a][b][3] += hi.y;
            }
        s = (s + 1 == 3) ? 0 : s + 1;
    }
#undef ISSUE_STAGE_H

#pragma unroll
    for (int mi = 0; mi < 2; mi++) {
        const int r0 = mbase + wr * 32 + mi * 16 + g;
#pragma unroll
        for (int ni = 0; ni < 8; ni++) {
            const int c = nbase + wc * 64 + ni * 8 + tg * 2;
            float x0 = fmaxf(facc[mi][ni][0], 0.f), x1 = fmaxf(facc[mi][ni][1], 0.f);
            float x2 = fmaxf(facc[mi][ni][2], 0.f), x3 = fmaxf(facc[mi][ni][3], 0.f);
            __half* H = (CDST == 0) ? g_Hs : g_H;
            *(__half2*)(H + (size_t)r0 * ND + c)       = __floats2half2_rn(x0, x1);
            *(__half2*)(H + (size_t)(r0 + 8) * ND + c) = __floats2half2_rn(x2, x3);
        }
    }
}

// ---------------- launch ----------------
extern "C" void kernel_launch(void* const* d_in, const int* in_sizes, int n_in,
                              void* d_out, int out_size) {
    const float* x   = (const float*)d_in[0];
    const float* sw1 = (const float*)d_in[1];
    const float* sw2 = (const float*)d_in[2];
    const float* rw1 = (const float*)d_in[3];
    const float* rw2 = (const float*)d_in[4];
    const float* rtw = (const float*)d_in[5];
    float* out = (float*)d_out;

    constexpr int NSMEM = 3 * 2 * 128 * 72 * 2;   // 110592 B

    auto s1 = gemm_h16acc<false, false, 0>;
    auto r1 = gemm_h16acc<true,  true,  3>;
    auto s2 = gemm_hmma<INTER, DIM, false, false, false, 1, 1, false>;
    auto r2 = gemm_hmma<INTER, DIM, true,  false, false, 2, 2, false>;
    cudaFuncSetAttribute(s1, cudaFuncAttributeMaxDynamicSharedMemorySize, NSMEM);
    cudaFuncSetAttribute(r1, cudaFuncAttributeMaxDynamicSharedMemorySize, NSMEM);
    cudaFuncSetAttribute(s2, cudaFuncAttributeMaxDynamicSharedMemorySize, NSMEM);
    cudaFuncSetAttribute(r2, cudaFuncAttributeMaxDynamicSharedMemorySize, NSMEM);

    // one-time side stream + fork/join events (created on the uncaptured correctness call)
    static cudaStream_t sB = nullptr;
    static cudaEvent_t  evF = nullptr, evJ = nullptr;
    if (!sB) {
        cudaStreamCreateWithFlags(&sB, cudaStreamNonBlocking);
        cudaEventCreateWithFlags(&evF, cudaEventDisableTiming);
        cudaEventCreateWithFlags(&evJ, cudaEventDisableTiming);
    }

    dim3 tb(32, 8);

    // ---- stream A (default): x convert, shared-expert chain ----
    cvtx_kernel<<<NT * DIM / 1024, 256>>>(x);                                   // launch 1
    cudaEventRecord(evF, 0);                                                    // fork point
    tcvt_kernel<<<dim3(INTER/64, DIM/64, 1),  tb>>>(sw1, 0, 0, DIM, INTER);     // 2
    tcvt_kernel<<<dim3(DIM/64, INTER/64, 1),  tb>>>(sw2, 1, 0, INTER, DIM);     // 3
    s1<<<dim3(INTER/128, NT/128), 256, NSMEM>>>();                              // 4  <- profiled
    s2<<<dim3(DIM/128,   NT/128), 256, NSMEM>>>(out);                           // 5

    // ---- stream B: routing + routed-expert chain (independent of s-chain) ----
    cudaStreamWaitEvent(sB, evF, 0);   // needs g_xh (cvtx)
    init_kernel   <<<(MAXROWS + 255) / 256, 256, 0, sB>>>();
    router_kernel <<<NT / 8, 256, 0, sB>>>(x, rtw);
    scan_kernel   <<<1, 32, 0, sB>>>();
    scatter_kernel<<<NT / 256, 256, 0, sB>>>();
    tcvt_kernel<<<dim3(INTER/64, DIM/64, NE), tb, 0, sB>>>(rw1, 0, (size_t)INTER * DIM, DIM, INTER);
    tcvt_kernel<<<dim3(DIM/64, INTER/64, NE), tb, 0, sB>>>(rw2, 1, (size_t)DIM * INTER, INTER, DIM);
    r1<<<dim3(INTER/128, MAXTILES), 256, NSMEM, sB>>>();
    r2<<<dim3(DIM/128,   MAXTILES), 256, NSMEM, sB>>>(out);
    cudaEventRecord(evJ, sB);

    // ---- join: combine needs s2 (stream A) and r2 (stream B) ----
    cudaStreamWaitEvent(0, evJ, 0);
    combine_kernel<<<NT, 256>>>(out);
}

// round 15
// speedup vs baseline: 1.1560x; 1.1560x over previous
#include <cuda_runtime.h>
#include <cuda_fp16.h>
#include <cstdint>

#define NT    8192
#define DIM   1024
#define INTER 4096
#define NE    8
#define MAXROWS  17408      // 2*NT + NE*128 (expert segments padded to 128)
#define MAXTILES 136        // MAXROWS/128

// ---------------- scratch (device globals: no allocations allowed) ----------------
__device__ __half g_xh[(size_t)NT * DIM];
__device__ __half g_Hs[(size_t)NT * INTER];                // shared-expert H (s-chain)
__device__ __half g_H[(size_t)MAXROWS * INTER];            // routed gathered H (r-chain)
__device__ __half g_w1t[(size_t)(NE + 1) * INTER * DIM];   // [1+E][INTER][DIM]  (W1^T, K-major)
__device__ __half g_w2t[(size_t)(NE + 1) * DIM * INTER];   // [1+E][DIM][INTER]  (W2^T, K-major)
__device__ int    g_perm[MAXROWS];
__device__ float  g_wperm[MAXROWS];
__device__ int    g_tok_e[NT * 2];
__device__ float  g_tok_w[NT * 2];
__device__ int    g_cnt[NE];
__device__ int    g_cursor[NE];
__device__ int    g_tile_e[MAXTILES];
__device__ int    g_tile_m[MAXTILES];
__device__ int    g_tile_end[MAXTILES];

// ---------------- PTX helpers ----------------
__device__ __forceinline__ uint32_t smem_u32(const void* p) {
    uint32_t a;
    asm("{ .reg .u64 t; cvta.to.shared.u64 t, %1; cvt.u32.u64 %0, t; }" : "=r"(a) : "l"(p));
    return a;
}
__device__ __forceinline__ void ldm4(uint32_t* r, uint32_t addr) {
    asm volatile("ldmatrix.sync.aligned.m8n8.x4.shared.b16 {%0,%1,%2,%3}, [%4];"
                 : "=r"(r[0]), "=r"(r[1]), "=r"(r[2]), "=r"(r[3]) : "r"(addr));
}
__device__ __forceinline__ void mma16816(float* d, const uint32_t* a, uint32_t b0, uint32_t b1) {
    asm volatile(
        "mma.sync.aligned.m16n8k16.row.col.f32.f16.f16.f32 "
        "{%0,%1,%2,%3},{%4,%5,%6,%7},{%8,%9},{%0,%1,%2,%3};"
        : "+f"(d[0]), "+f"(d[1]), "+f"(d[2]), "+f"(d[3])
        : "r"(a[0]), "r"(a[1]), "r"(a[2]), "r"(a[3]), "r"(b0), "r"(b1));
}
__device__ __forceinline__ void cpa16(uint32_t dst, const void* src) {
    asm volatile("cp.async.cg.shared.global [%0], [%1], 16;" :: "r"(dst), "l"(src));
}

// ---------------- small kernels ----------------
__global__ void init_kernel() {
    int i = blockIdx.x * 256 + threadIdx.x;
    if (i < NE) g_cnt[i] = 0;
    if (i < MAXROWS) { g_perm[i] = 0; g_wperm[i] = 0.0f; }
}

__global__ void router_kernel(const float* __restrict__ x, const float* __restrict__ rw) {
    int w = (blockIdx.x * blockDim.x + threadIdx.x) >> 5;
    int lane = threadIdx.x & 31;
    if (w >= NT) return;
    const float* xr = x + (size_t)w * DIM;
    float acc[NE];
#pragma unroll
    for (int e = 0; e < NE; e++) acc[e] = 0.f;
    for (int k = lane; k < DIM; k += 32) {
        float xv = xr[k];
        const float4 wa = *(const float4*)(rw + k * NE);
        const float4 wb = *(const float4*)(rw + k * NE + 4);
        acc[0] += xv*wa.x; acc[1] += xv*wa.y; acc[2] += xv*wa.z; acc[3] += xv*wa.w;
        acc[4] += xv*wb.x; acc[5] += xv*wb.y; acc[6] += xv*wb.z; acc[7] += xv*wb.w;
    }
#pragma unroll
    for (int off = 16; off > 0; off >>= 1)
#pragma unroll
        for (int e = 0; e < NE; e++) acc[e] += __shfl_xor_sync(0xffffffffu, acc[e], off);
    if (lane == 0) {
        float v0 = -1e30f, v1 = -1e30f; int i0 = 0, i1 = 0;
#pragma unroll
        for (int e = 0; e < NE; e++) {
            float v = acc[e];
            if (v > v0) { v1 = v0; i1 = i0; v0 = v; i0 = e; }
            else if (v > v1) { v1 = v; i1 = e; }
        }
        float w0 = 1.0f / (1.0f + expf(v1 - v0));
        float w1 = 1.0f - w0;
        g_tok_e[2*w] = i0; g_tok_e[2*w+1] = i1;
        g_tok_w[2*w] = w0; g_tok_w[2*w+1] = w1;
        atomicAdd(&g_cnt[i0], 1); atomicAdd(&g_cnt[i1], 1);
    }
}

__global__ void scan_kernel() {
    if (threadIdx.x != 0 || blockIdx.x != 0) return;
    int off = 0, tile = 0;
    for (int e = 0; e < NE; e++) {
        int c = g_cnt[e];
        g_cursor[e] = off;
        int end = off + c;
        int nt = (c + 127) >> 7;
        for (int i = 0; i < nt; i++) {
            g_tile_e[tile] = e; g_tile_m[tile] = off + (i << 7); g_tile_end[tile] = end; tile++;
        }
        off += nt << 7;
    }
    for (; tile < MAXTILES; tile++) g_tile_e[tile] = -1;
}

__global__ void scatter_kernel() {
    int t = blockIdx.x * 256 + threadIdx.x;
    if (t >= NT) return;
#pragma unroll
    for (int k = 0; k < 2; k++) {
        int e = g_tok_e[2*t + k];
        int p = atomicAdd(&g_cursor[e], 1);
        g_perm[p] = t;
        g_wperm[p] = g_tok_w[2*t + k];
    }
}

__global__ void cvtx_kernel(const float* __restrict__ x) {
    size_t i = ((size_t)blockIdx.x * 256 + threadIdx.x) * 4;
    float4 v = *(const float4*)(x + i);
    union { __half2 h[2]; uint2 u; } pk;
    pk.h[0] = __floats2half2_rn(v.x, v.y);
    pk.h[1] = __floats2half2_rn(v.z, v.w);
    *(uint2*)(g_xh + i) = pk.u;
}

// transpose + convert: in fp32 [R,C] (row-major) -> out fp16 [C,R] (K-major for MMA)
__global__ void tcvt_kernel(const float* __restrict__ in, int w2sel, size_t outOff, int R, int C) {
    __shared__ float t[64][65];
    int z = blockIdx.z;
    in += (size_t)z * R * C;
    __half* out = (w2sel ? g_w2t : g_w1t) + outOff + (size_t)z * R * C;
    int r0 = blockIdx.y * 64, c0 = blockIdx.x * 64;
    int tx = threadIdx.x, ty = threadIdx.y;
#pragma unroll
    for (int i = 0; i < 8; i++) {
        int row = ty + i * 8;
        const float* p = in + (size_t)(r0 + row) * C + c0 + tx;
        t[row][tx]      = p[0];
        t[row][tx + 32] = p[32];
    }
    __syncthreads();
#pragma unroll
    for (int i = 0; i < 8; i++) {
        int c = ty + i * 8;
        __half2 v = __floats2half2_rn(t[2*tx][c], t[2*tx + 1][c]);
        *(__half2*)(out + (size_t)(c0 + c) * R + r0 + 2*tx) = v;
    }
}

// ---------------- fp16 HMMA GEMM (narrow, f32-acc): BM=BN=128, BK=64, warp 32x64, 2 CTA/SM ------
// ASRC: 0 -> g_xh, 1 -> g_Hs, 2 -> g_H
// CDST: 0 -> g_Hs (fp16, relu), 1 -> outp (fp32 stores), 2 -> outp (ATOMIC scatter-add, weighted,
//        guarded by segEnd), 3 -> g_H (fp16, relu)
template<int KD, int ND, bool GROUPED, bool GATHER, bool RELU, int CDST, int ASRC, bool W1SEL>
__global__ void __launch_bounds__(256, 2) gemm_hmma(float* __restrict__ outp) {
    constexpr int BK = 64, KT = KD / BK;
    constexpr int AST = 72;
    constexpr int TILEB = 128 * AST * 2;
    constexpr int STAGEB = 2 * TILEB;
    extern __shared__ __half sm[];

    const __half* A = (ASRC == 0) ? g_xh : ((ASRC == 1) ? g_Hs : g_H);
    const __half* B = W1SEL ? g_w1t : g_w2t;
    int mbase, segEnd = 0;
    if (GROUPED) {
        int e = g_tile_e[blockIdx.y];
        if (e < 0) return;
        mbase = g_tile_m[blockIdx.y];
        segEnd = g_tile_end[blockIdx.y];
        B += (size_t)(1 + e) * KD * ND;
    } else {
        mbase = blockIdx.y * 128;
    }
    const int nbase = blockIdx.x * 128;
    const int tid = threadIdx.x, warp = tid >> 5, lane = tid & 31;
    const int wr = warp & 3, wc = warp >> 2;
    const int g = lane >> 2, tg = lane & 3;

    const __half* aPtr[4]; const __half* bPtr[4];
    uint32_t sAoff[4], sBoff[4];
    const uint32_t smb = smem_u32(sm);
#pragma unroll
    for (int i = 0; i < 4; i++) {
        int idx = tid + i * 256, row = idx >> 3, ch = idx & 7;
        sAoff[i] = smb + (row * AST + ch * 8) * 2;
        sBoff[i] = sAoff[i] + TILEB;
        int ar = mbase + row;
        if (GATHER) ar = g_perm[ar];
        aPtr[i] = A + (size_t)ar * KD + ch * 8;
        bPtr[i] = B + (size_t)(nbase + row) * KD + ch * 8;
    }

    const int lr = (lane & 7) + ((lane >> 3) & 1) * 8;
    const int lk = (lane >> 4) * 8;
    const uint32_t aBase = smb + ((wr * 32 + lr) * AST + lk) * 2;
    const uint32_t bBase = smb + TILEB + ((wc * 64 + lr) * AST + lk) * 2;
    constexpr int ROW16 = 16 * AST * 2;

    float acc[2][8][4];
#pragma unroll
    for (int a = 0; a < 2; a++)
#pragma unroll
        for (int b = 0; b < 8; b++)
#pragma unroll
            for (int c = 0; c < 4; c++) acc[a][b][c] = 0.f;

#define ISSUE_STAGE_N(kt_, s_) do {                                           \
        uint32_t so_ = (uint32_t)(s_) * STAGEB;                               \
        _Pragma("unroll")                                                     \
        for (int i_ = 0; i_ < 4; i_++) cpa16(sAoff[i_] + so_, aPtr[i_] + (kt_) * BK); \
        _Pragma("unroll")                                                     \
        for (int i_ = 0; i_ < 4; i_++) cpa16(sBoff[i_] + so_, bPtr[i_] + (kt_) * BK); \
        asm volatile("cp.async.commit_group;" ::: "memory");                  \
    } while (0)

    ISSUE_STAGE_N(0, 0);
    ISSUE_STAGE_N(1, 1);

    int s = 0;
    for (int kt = 0; kt < KT; kt++) {
        if (kt + 1 < KT) asm volatile("cp.async.wait_group 1;" ::: "memory");
        else             asm volatile("cp.async.wait_group 0;" ::: "memory");
        __syncthreads();
        if (kt + 2 < KT) {
            int s2 = s + 2; if (s2 >= 3) s2 -= 3;
            ISSUE_STAGE_N(kt + 2, s2);
        }
        const uint32_t ab = aBase + s * STAGEB;
        const uint32_t bb = bBase + s * STAGEB;
#pragma unroll
        for (int kg = 0; kg < 4; kg++) {
            uint32_t af[2][4];
            ldm4(af[0], ab + kg * 32);
            ldm4(af[1], ab + ROW16 + kg * 32);
#pragma unroll
            for (int nj = 0; nj < 4; nj++) {
                uint32_t bf[4];
                ldm4(bf, bb + nj * ROW16 + kg * 32);
                mma16816(acc[0][2*nj],     af[0], bf[0], bf[2]);
                mma16816(acc[0][2*nj + 1], af[0], bf[1], bf[3]);
                mma16816(acc[1][2*nj],     af[1], bf[0], bf[2]);
                mma16816(acc[1][2*nj + 1], af[1], bf[1], bf[3]);
            }
        }
        s = (s + 1 == 3) ? 0 : s + 1;
    }
#undef ISSUE_STAGE_N

#pragma unroll
    for (int mi = 0; mi < 2; mi++) {
        const int r0 = mbase + wr * 32 + mi * 16 + g;
        const int r1 = r0 + 8;
        if (CDST == 2) {
            // weighted scatter-add into out; skip padding rows (>= segEnd)
            bool v0 = r0 < segEnd, v1 = r1 < segEnd;
            int t0 = 0, t1 = 0; float w0 = 0.f, w1 = 0.f;
            if (v0) { t0 = g_perm[r0]; w0 = g_wperm[r0]; }
            if (v1) { t1 = g_perm[r1]; w1 = g_wperm[r1]; }
#pragma unroll
            for (int ni = 0; ni < 8; ni++) {
                const int c = nbase + wc * 64 + ni * 8 + tg * 2;
                if (v0) {
                    atomicAdd(&outp[(size_t)t0 * ND + c],     w0 * acc[mi][ni][0]);
                    atomicAdd(&outp[(size_t)t0 * ND + c + 1], w0 * acc[mi][ni][1]);
                }
                if (v1) {
                    atomicAdd(&outp[(size_t)t1 * ND + c],     w1 * acc[mi][ni][2]);
                    atomicAdd(&outp[(size_t)t1 * ND + c + 1], w1 * acc[mi][ni][3]);
                }
            }
        } else {
#pragma unroll
            for (int ni = 0; ni < 8; ni++) {
                const int c = nbase + wc * 64 + ni * 8 + tg * 2;
                float x0 = acc[mi][ni][0], x1 = acc[mi][ni][1];
                float x2 = acc[mi][ni][2], x3 = acc[mi][ni][3];
                if (RELU) { x0 = fmaxf(x0, 0.f); x1 = fmaxf(x1, 0.f);
                            x2 = fmaxf(x2, 0.f); x3 = fmaxf(x3, 0.f); }
                if (CDST == 0 || CDST == 3) {
                    __half* H = (CDST == 0) ? g_Hs : g_H;
                    *(__half2*)(H + (size_t)r0 * ND + c) = __floats2half2_rn(x0, x1);
                    *(__half2*)(H + (size_t)r1 * ND + c) = __floats2half2_rn(x2, x3);
                } else {
                    *(float2*)(outp + (size_t)r0 * ND + c) = make_float2(x0, x1);
                    *(float2*)(outp + (size_t)r1 * ND + c) = make_float2(x2, x3);
                }
            }
        }
    }
}

// ---------------- launch ----------------
extern "C" void kernel_launch(void* const* d_in, const int* in_sizes, int n_in,
                              void* d_out, int out_size) {
    const float* x   = (const float*)d_in[0];
    const float* sw1 = (const float*)d_in[1];
    const float* sw2 = (const float*)d_in[2];
    const float* rw1 = (const float*)d_in[3];
    const float* rw2 = (const float*)d_in[4];
    const float* rtw = (const float*)d_in[5];
    float* out = (float*)d_out;

    constexpr int NSMEM = 3 * 2 * 128 * 72 * 2;   // 110592 B

    auto s1 = gemm_hmma<DIM,   INTER, false, false, true,  0, 0, true >;
    auto s2 = gemm_hmma<INTER, DIM,   false, false, false, 1, 1, false>;
    auto r1 = gemm_hmma<DIM,   INTER, true,  true,  true,  3, 0, true >;
    auto r2 = gemm_hmma<INTER, DIM,   true,  false, false, 2, 2, false>;
    cudaFuncSetAttribute(s1, cudaFuncAttributeMaxDynamicSharedMemorySize, NSMEM);
    cudaFuncSetAttribute(s2, cudaFuncAttributeMaxDynamicSharedMemorySize, NSMEM);
    cudaFuncSetAttribute(r1, cudaFuncAttributeMaxDynamicSharedMemorySize, NSMEM);
    cudaFuncSetAttribute(r2, cudaFuncAttributeMaxDynamicSharedMemorySize, NSMEM);

    // one-time side stream + fork/join events (created on the uncaptured correctness call)
    static cudaStream_t sB = nullptr;
    static cudaEvent_t  evF = nullptr, evS2 = nullptr, evJ = nullptr;
    if (!sB) {
        cudaStreamCreateWithFlags(&sB, cudaStreamNonBlocking);
        cudaEventCreateWithFlags(&evF,  cudaEventDisableTiming);
        cudaEventCreateWithFlags(&evS2, cudaEventDisableTiming);
        cudaEventCreateWithFlags(&evJ,  cudaEventDisableTiming);
    }

    dim3 tb(32, 8);

    // ---- stream A (default): x convert, shared-expert chain ----
    cvtx_kernel<<<NT * DIM / 1024, 256>>>(x);                                   // launch 1
    cudaEventRecord(evF, 0);                                                    // fork point
    tcvt_kernel<<<dim3(INTER/64, DIM/64, 1),  tb>>>(sw1, 0, 0, DIM, INTER);     // 2
    tcvt_kernel<<<dim3(DIM/64, INTER/64, 1),  tb>>>(sw2, 1, 0, INTER, DIM);     // 3
    s1<<<dim3(INTER/128, NT/128), 256, NSMEM>>>(out);                           // 4  <- profiled
    s2<<<dim3(DIM/128,   NT/128), 256, NSMEM>>>(out);                           // 5
    cudaEventRecord(evS2, 0);                                                   // out fully written

    // ---- stream B: routing + routed-expert chain ----
    cudaStreamWaitEvent(sB, evF, 0);   // needs g_xh (cvtx)
    init_kernel   <<<(MAXROWS + 255) / 256, 256, 0, sB>>>();
    router_kernel <<<NT / 8, 256, 0, sB>>>(x, rtw);
    scan_kernel   <<<1, 32, 0, sB>>>();
    scatter_kernel<<<NT / 256, 256, 0, sB>>>();
    tcvt_kernel<<<dim3(INTER/64, DIM/64, NE), tb, 0, sB>>>(rw1, 0, (size_t)INTER * DIM, DIM, INTER);
    tcvt_kernel<<<dim3(DIM/64, INTER/64, NE), tb, 0, sB>>>(rw2, 1, (size_t)DIM * INTER, INTER, DIM);
    r1<<<dim3(INTER/128, MAXTILES), 256, NSMEM, sB>>>(out);
    cudaStreamWaitEvent(sB, evS2, 0);  // r2 atomically adds into out -> s2 must be done
    r2<<<dim3(DIM/128,   MAXTILES), 256, NSMEM, sB>>>(out);
    cudaEventRecord(evJ, sB);

    // ---- join back to origin stream ----
    cudaStreamWaitEvent(0, evJ, 0);
}

// round 17
// speedup vs baseline: 1.1648x; 1.0076x over previous
#include <cuda_runtime.h>
#include <cuda_fp16.h>
#include <cstdint>

#define NT    8192
#define DIM   1024
#define INTER 4096
#define NE    8
#define MAXROWS  17408      // 2*NT + NE*128 (expert segments padded to 128)
#define MAXTILES 136        // MAXROWS/128

// ---------------- scratch (device globals: no allocations allowed) ----------------
__device__ __half g_xh[(size_t)NT * DIM];
__device__ __half g_Hs[(size_t)NT * INTER];                // shared-expert H (s-chain)
__device__ __half g_H[(size_t)MAXROWS * INTER];            // routed gathered H (r-chain)
__device__ __half g_w1t[(size_t)(NE + 1) * INTER * DIM];   // [1+E][INTER][DIM]  (W1^T, K-major)
__device__ __half g_w2t[(size_t)(NE + 1) * DIM * INTER];   // [1+E][DIM][INTER]  (W2^T, K-major)
__device__ int    g_perm[MAXROWS];
__device__ float  g_wperm[MAXROWS];
__device__ int    g_tok_e[NT * 2];
__device__ float  g_tok_w[NT * 2];
__device__ int    g_cnt[NE];
__device__ int    g_cursor[NE];
__device__ int    g_tile_e[MAXTILES];
__device__ int    g_tile_m[MAXTILES];
__device__ int    g_tile_end[MAXTILES];

// ---------------- PTX helpers ----------------
__device__ __forceinline__ uint32_t smem_u32(const void* p) {
    uint32_t a;
    asm("{ .reg .u64 t; cvta.to.shared.u64 t, %1; cvt.u32.u64 %0, t; }" : "=r"(a) : "l"(p));
    return a;
}
__device__ __forceinline__ void ldm4(uint32_t* r, uint32_t addr) {
    asm volatile("ldmatrix.sync.aligned.m8n8.x4.shared.b16 {%0,%1,%2,%3}, [%4];"
                 : "=r"(r[0]), "=r"(r[1]), "=r"(r[2]), "=r"(r[3]) : "r"(addr));
}
__device__ __forceinline__ void mma16816(float* d, const uint32_t* a, uint32_t b0, uint32_t b1) {
    asm volatile(
        "mma.sync.aligned.m16n8k16.row.col.f32.f16.f16.f32 "
        "{%0,%1,%2,%3},{%4,%5,%6,%7},{%8,%9},{%0,%1,%2,%3};"
        : "+f"(d[0]), "+f"(d[1]), "+f"(d[2]), "+f"(d[3])
        : "r"(a[0]), "r"(a[1]), "r"(a[2]), "r"(a[3]), "r"(b0), "r"(b1));
}
__device__ __forceinline__ void cpa16(uint32_t dst, const void* src) {
    asm volatile("cp.async.cg.shared.global [%0], [%1], 16;" :: "r"(dst), "l"(src));
}

// ---------------- small kernels ----------------
__global__ void init_kernel() {
    int i = blockIdx.x * 256 + threadIdx.x;
    if (i < NE) g_cnt[i] = 0;
    if (i < MAXROWS) { g_perm[i] = 0; g_wperm[i] = 0.0f; }
}

__global__ void router_kernel(const float* __restrict__ x, const float* __restrict__ rw) {
    int w = (blockIdx.x * blockDim.x + threadIdx.x) >> 5;
    int lane = threadIdx.x & 31;
    if (w >= NT) return;
    const float* xr = x + (size_t)w * DIM;
    float acc[NE];
#pragma unroll
    for (int e = 0; e < NE; e++) acc[e] = 0.f;
    for (int k = lane; k < DIM; k += 32) {
        float xv = xr[k];
        const float4 wa = *(const float4*)(rw + k * NE);
        const float4 wb = *(const float4*)(rw + k * NE + 4);
        acc[0] += xv*wa.x; acc[1] += xv*wa.y; acc[2] += xv*wa.z; acc[3] += xv*wa.w;
        acc[4] += xv*wb.x; acc[5] += xv*wb.y; acc[6] += xv*wb.z; acc[7] += xv*wb.w;
    }
#pragma unroll
    for (int off = 16; off > 0; off >>= 1)
#pragma unroll
        for (int e = 0; e < NE; e++) acc[e] += __shfl_xor_sync(0xffffffffu, acc[e], off);
    if (lane == 0) {
        float v0 = -1e30f, v1 = -1e30f; int i0 = 0, i1 = 0;
#pragma unroll
        for (int e = 0; e < NE; e++) {
            float v = acc[e];
            if (v > v0) { v1 = v0; i1 = i0; v0 = v; i0 = e; }
            else if (v > v1) { v1 = v; i1 = e; }
        }
        float w0 = 1.0f / (1.0f + expf(v1 - v0));
        float w1 = 1.0f - w0;
        g_tok_e[2*w] = i0; g_tok_e[2*w+1] = i1;
        g_tok_w[2*w] = w0; g_tok_w[2*w+1] = w1;
        atomicAdd(&g_cnt[i0], 1); atomicAdd(&g_cnt[i1], 1);
    }
}

__global__ void scan_kernel() {
    if (threadIdx.x != 0 || blockIdx.x != 0) return;
    int off = 0, tile = 0;
    for (int e = 0; e < NE; e++) {
        int c = g_cnt[e];
        g_cursor[e] = off;
        int end = off + c;
        int nt = (c + 127) >> 7;
        for (int i = 0; i < nt; i++) {
            g_tile_e[tile] = e; g_tile_m[tile] = off + (i << 7); g_tile_end[tile] = end; tile++;
        }
        off += nt << 7;
    }
    for (; tile < MAXTILES; tile++) g_tile_e[tile] = -1;
}

__global__ void scatter_kernel() {
    int t = blockIdx.x * 256 + threadIdx.x;
    if (t >= NT) return;
#pragma unroll
    for (int k = 0; k < 2; k++) {
        int e = g_tok_e[2*t + k];
        int p = atomicAdd(&g_cursor[e], 1);
        g_perm[p] = t;
        g_wperm[p] = g_tok_w[2*t + k];
    }
}

__global__ void cvtx_kernel(const float* __restrict__ x) {
    size_t i = ((size_t)blockIdx.x * 256 + threadIdx.x) * 4;
    float4 v = *(const float4*)(x + i);
    union { __half2 h[2]; uint2 u; } pk;
    pk.h[0] = __floats2half2_rn(v.x, v.y);
    pk.h[1] = __floats2half2_rn(v.z, v.w);
    *(uint2*)(g_xh + i) = pk.u;
}

// transpose + convert: in fp32 [R,C] (row-major) -> out fp16 [C,R] (K-major for MMA)
__global__ void tcvt_kernel(const float* __restrict__ in, int w2sel, size_t outOff, int R, int C) {
    __shared__ float t[64][65];
    int z = blockIdx.z;
    in += (size_t)z * R * C;
    __half* out = (w2sel ? g_w2t : g_w1t) + outOff + (size_t)z * R * C;
    int r0 = blockIdx.y * 64, c0 = blockIdx.x * 64;
    int tx = threadIdx.x, ty = threadIdx.y;
#pragma unroll
    for (int i = 0; i < 8; i++) {
        int row = ty + i * 8;
        const float* p = in + (size_t)(r0 + row) * C + c0 + tx;
        t[row][tx]      = p[0];
        t[row][tx + 32] = p[32];
    }
    __syncthreads();
#pragma unroll
    for (int i = 0; i < 8; i++) {
        int c = ty + i * 8;
        __half2 v = __floats2half2_rn(t[2*tx][c], t[2*tx + 1][c]);
        *(__half2*)(out + (size_t)(c0 + c) * R + r0 + 2*tx) = v;
    }
}

// ---------------- fp16 HMMA GEMM (narrow, f32-acc): BM=BN=128, BK=64, warp 32x64, 2 CTA/SM ------
// ASRC: 0 -> g_xh, 1 -> g_Hs, 2 -> g_H
// CDST: 0 -> g_Hs (fp16, relu), 1 -> outp (fp32 stores), 2 -> outp (ATOMIC scatter-add, weighted,
//        guarded by segEnd), 3 -> g_H (fp16, relu)
template<int KD, int ND, bool GROUPED, bool GATHER, bool RELU, int CDST, int ASRC, bool W1SEL>
__global__ void __launch_bounds__(256, 2) gemm_hmma(float* __restrict__ outp) {
    constexpr int BK = 64, KT = KD / BK;
    constexpr int AST = 72;
    constexpr int TILEB = 128 * AST * 2;
    constexpr int STAGEB = 2 * TILEB;
    extern __shared__ __half sm[];

    const __half* A = (ASRC == 0) ? g_xh : ((ASRC == 1) ? g_Hs : g_H);
    const __half* B = W1SEL ? g_w1t : g_w2t;
    int mbase, segEnd = 0;
    if (GROUPED) {
        int e = g_tile_e[blockIdx.y];
        if (e < 0) return;
        mbase = g_tile_m[blockIdx.y];
        segEnd = g_tile_end[blockIdx.y];
        B += (size_t)(1 + e) * KD * ND;
    } else {
        mbase = blockIdx.y * 128;
    }
    const int nbase = blockIdx.x * 128;
    const int tid = threadIdx.x, warp = tid >> 5, lane = tid & 31;
    const int wr = warp & 3, wc = warp >> 2;
    const int g = lane >> 2, tg = lane & 3;

    const __half* aPtr[4]; const __half* bPtr[4];
    uint32_t sAoff[4], sBoff[4];
    const uint32_t smb = smem_u32(sm);
#pragma unroll
    for (int i = 0; i < 4; i++) {
        int idx = tid + i * 256, row = idx >> 3, ch = idx & 7;
        sAoff[i] = smb + (row * AST + ch * 8) * 2;
        sBoff[i] = sAoff[i] + TILEB;
        int ar = mbase + row;
        if (GATHER) ar = g_perm[ar];
        aPtr[i] = A + (size_t)ar * KD + ch * 8;
        bPtr[i] = B + (size_t)(nbase + row) * KD + ch * 8;
    }

    const int lr = (lane & 7) + ((lane >> 3) & 1) * 8;
    const int lk = (lane >> 4) * 8;
    const uint32_t aBase = smb + ((wr * 32 + lr) * AST + lk) * 2;
    const uint32_t bBase = smb + TILEB + ((wc * 64 + lr) * AST + lk) * 2;
    constexpr int ROW16 = 16 * AST * 2;

    float acc[2][8][4];
#pragma unroll
    for (int a = 0; a < 2; a++)
#pragma unroll
        for (int b = 0; b < 8; b++)
#pragma unroll
            for (int c = 0; c < 4; c++) acc[a][b][c] = 0.f;

#define ISSUE_STAGE_N(kt_, s_) do {                                           \
        uint32_t so_ = (uint32_t)(s_) * STAGEB;                               \
        _Pragma("unroll")                                                     \
        for (int i_ = 0; i_ < 4; i_++) cpa16(sAoff[i_] + so_, aPtr[i_] + (kt_) * BK); \
        _Pragma("unroll")                                                     \
        for (int i_ = 0; i_ < 4; i_++) cpa16(sBoff[i_] + so_, bPtr[i_] + (kt_) * BK); \
        asm volatile("cp.async.commit_group;" ::: "memory");                  \
    } while (0)

    ISSUE_STAGE_N(0, 0);
    ISSUE_STAGE_N(1, 1);

    int s = 0;
    for (int kt = 0; kt < KT; kt++) {
        if (kt + 1 < KT) asm volatile("cp.async.wait_group 1;" ::: "memory");
        else             asm volatile("cp.async.wait_group 0;" ::: "memory");
        __syncthreads();
        if (kt + 2 < KT) {
            int s2 = s + 2; if (s2 >= 3) s2 -= 3;
            ISSUE_STAGE_N(kt + 2, s2);
        }
        const uint32_t ab = aBase + s * STAGEB;
        const uint32_t bb = bBase + s * STAGEB;
#pragma unroll
        for (int kg = 0; kg < 4; kg++) {
            uint32_t af[2][4];
            ldm4(af[0], ab + kg * 32);
            ldm4(af[1], ab + ROW16 + kg * 32);
#pragma unroll
            for (int nj = 0; nj < 4; nj++) {
                uint32_t bf[4];
                ldm4(bf, bb + nj * ROW16 + kg * 32);
                mma16816(acc[0][2*nj],     af[0], bf[0], bf[2]);
                mma16816(acc[0][2*nj + 1], af[0], bf[1], bf[3]);
                mma16816(acc[1][2*nj],     af[1], bf[0], bf[2]);
                mma16816(acc[1][2*nj + 1], af[1], bf[1], bf[3]);
            }
        }
        s = (s + 1 == 3) ? 0 : s + 1;
    }
#undef ISSUE_STAGE_N

#pragma unroll
    for (int mi = 0; mi < 2; mi++) {
        const int r0 = mbase + wr * 32 + mi * 16 + g;
        const int r1 = r0 + 8;
        if (CDST == 2) {
            // weighted scatter-add into out; skip padding rows (>= segEnd)
            bool v0 = r0 < segEnd, v1 = r1 < segEnd;
            int t0 = 0, t1 = 0; float w0 = 0.f, w1 = 0.f;
            if (v0) { t0 = g_perm[r0]; w0 = g_wperm[r0]; }
            if (v1) { t1 = g_perm[r1]; w1 = g_wperm[r1]; }
#pragma unroll
            for (int ni = 0; ni < 8; ni++) {
                const int c = nbase + wc * 64 + ni * 8 + tg * 2;
                if (v0) {
                    atomicAdd(&outp[(size_t)t0 * ND + c],     w0 * acc[mi][ni][0]);
                    atomicAdd(&outp[(size_t)t0 * ND + c + 1], w0 * acc[mi][ni][1]);
                }
                if (v1) {
                    atomicAdd(&outp[(size_t)t1 * ND + c],     w1 * acc[mi][ni][2]);
                    atomicAdd(&outp[(size_t)t1 * ND + c + 1], w1 * acc[mi][ni][3]);
                }
            }
        } else {
#pragma unroll
            for (int ni = 0; ni < 8; ni++) {
                const int c = nbase + wc * 64 + ni * 8 + tg * 2;
                float x0 = acc[mi][ni][0], x1 = acc[mi][ni][1];
                float x2 = acc[mi][ni][2], x3 = acc[mi][ni][3];
                if (RELU) { x0 = fmaxf(x0, 0.f); x1 = fmaxf(x1, 0.f);
                            x2 = fmaxf(x2, 0.f); x3 = fmaxf(x3, 0.f); }
                if (CDST == 0 || CDST == 3) {
                    __half* H = (CDST == 0) ? g_Hs : g_H;
                    *(__half2*)(H + (size_t)r0 * ND + c) = __floats2half2_rn(x0, x1);
                    *(__half2*)(H + (size_t)r1 * ND + c) = __floats2half2_rn(x2, x3);
                } else {
                    *(float2*)(outp + (size_t)r0 * ND + c) = make_float2(x0, x1);
                    *(float2*)(outp + (size_t)r1 * ND + c) = make_float2(x2, x3);
                }
            }
        }
    }
}

// ---------------- launch ----------------
extern "C" void kernel_launch(void* const* d_in, const int* in_sizes, int n_in,
                              void* d_out, int out_size) {
    const float* x   = (const float*)d_in[0];
    const float* sw1 = (const float*)d_in[1];
    const float* sw2 = (const float*)d_in[2];
    const float* rw1 = (const float*)d_in[3];
    const float* rw2 = (const float*)d_in[4];
    const float* rtw = (const float*)d_in[5];
    float* out = (float*)d_out;

    constexpr int NSMEM = 3 * 2 * 128 * 72 * 2;   // 110592 B

    auto s1 = gemm_hmma<DIM,   INTER, false, false, true,  0, 0, true >;
    auto s2 = gemm_hmma<INTER, DIM,   false, false, false, 1, 1, false>;
    auto r1 = gemm_hmma<DIM,   INTER, true,  true,  true,  3, 0, true >;
    auto r2 = gemm_hmma<INTER, DIM,   true,  false, false, 2, 2, false>;
    cudaFuncSetAttribute(s1, cudaFuncAttributeMaxDynamicSharedMemorySize, NSMEM);
    cudaFuncSetAttribute(s2, cudaFuncAttributeMaxDynamicSharedMemorySize, NSMEM);
    cudaFuncSetAttribute(r1, cudaFuncAttributeMaxDynamicSharedMemorySize, NSMEM);
    cudaFuncSetAttribute(r2, cudaFuncAttributeMaxDynamicSharedMemorySize, NSMEM);

    // one-time side streams + events (created on the uncaptured correctness call)
    static cudaStream_t sB = nullptr, sC = nullptr;
    static cudaEvent_t  evStart = nullptr, evF = nullptr, evW1 = nullptr, evW2 = nullptr,
                        evRoute = nullptr, evS2 = nullptr, evJB = nullptr, evJC = nullptr;
    if (!sB) {
        cudaStreamCreateWithFlags(&sB, cudaStreamNonBlocking);
        cudaStreamCreateWithFlags(&sC, cudaStreamNonBlocking);
        cudaEventCreateWithFlags(&evStart, cudaEventDisableTiming);
        cudaEventCreateWithFlags(&evF,     cudaEventDisableTiming);
        cudaEventCreateWithFlags(&evW1,    cudaEventDisableTiming);
        cudaEventCreateWithFlags(&evW2,    cudaEventDisableTiming);
        cudaEventCreateWithFlags(&evRoute, cudaEventDisableTiming);
        cudaEventCreateWithFlags(&evS2,    cudaEventDisableTiming);
        cudaEventCreateWithFlags(&evJB,    cudaEventDisableTiming);
        cudaEventCreateWithFlags(&evJC,    cudaEventDisableTiming);
    }

    dim3 tb(32, 8);

    // ---- fork: side streams must first wait on an event recorded in the captured stream ----
    cudaEventRecord(evStart, 0);
    cudaStreamWaitEvent(sB, evStart, 0);
    cudaStreamWaitEvent(sC, evStart, 0);

    // ---- stream A (default): x convert, then shared-expert GEMM chain ----
    cvtx_kernel<<<NT * DIM / 1024, 256>>>(x);
    cudaEventRecord(evF, 0);                                                    // g_xh ready

    // ---- stream B: weight converts (independent of x) overlap cvtx ----
    tcvt_kernel<<<dim3(INTER/64, DIM/64, 1),  tb, 0, sB>>>(sw1, 0, 0, DIM, INTER);
    cudaEventRecord(evW1, sB);
    tcvt_kernel<<<dim3(DIM/64, INTER/64, 1),  tb, 0, sB>>>(sw2, 1, 0, INTER, DIM);
    cudaEventRecord(evW2, sB);

    cudaStreamWaitEvent(0, evW1, 0);
    s1<<<dim3(INTER/128, NT/128), 256, NSMEM>>>(out);
    cudaStreamWaitEvent(0, evW2, 0);
    s2<<<dim3(DIM/128,   NT/128), 256, NSMEM>>>(out);
    cudaEventRecord(evS2, 0);                                                   // out fully written

    // ---- stream C: routing (reads fp32 x directly; starts at fork) ----
    init_kernel   <<<(MAXROWS + 255) / 256, 256, 0, sC>>>();
    router_kernel <<<NT / 8, 256, 0, sC>>>(x, rtw);
    scan_kernel   <<<1, 32, 0, sC>>>();
    scatter_kernel<<<NT / 256, 256, 0, sC>>>();
    cudaEventRecord(evRoute, sC);

    // ---- stream B (cont.): routed weight converts, then routed GEMM chain ----
    tcvt_kernel<<<dim3(INTER/64, DIM/64, NE), tb, 0, sB>>>(rw1, 0, (size_t)INTER * DIM, DIM, INTER);
    tcvt_kernel<<<dim3(DIM/64, INTER/64, NE), tb, 0, sB>>>(rw2, 1, (size_t)DIM * INTER, INTER, DIM);
    cudaStreamWaitEvent(sB, evRoute, 0);   // needs g_perm/g_tile_* (scan+scatter)
    cudaStreamWaitEvent(sB, evF, 0);       // needs g_xh for the gather
    r1<<<dim3(INTER/128, MAXTILES), 256, NSMEM, sB>>>(out);
    cudaStreamWaitEvent(sB, evS2, 0);      // r2 atomically adds into out -> s2 must be done
    r2<<<dim3(DIM/128,   MAXTILES), 256, NSMEM, sB>>>(out);
    cudaEventRecord(evJB, sB);
    cudaEventRecord(evJC, sC);

    // ---- join all side streams back to origin ----
    cudaStreamWaitEvent(0, evJB, 0);
    cudaStreamWaitEvent(0, evJC, 0);
}